// round 2
// baseline (speedup 1.0000x reference)
#include <cuda_runtime.h>

#define Bn   2
#define Sn   2048
#define Hn   8
#define DMn  512
#define HDn  64
#define NRn  513
#define BHn  (Bn*Hn)

#define BI   16     // query rows per attention CTA
#define BJ   128    // key/value chunk

// ---------------- scratch (static device allocations are allowed) ----------
__device__ float g_Q[BHn*Sn*HDn];                 // pre-scaled by 1/8
__device__ float g_K[BHn*Sn*HDn];
__device__ float g_V[BHn*Sn*HDn];
__device__ float g_REL[(size_t)BHn*Sn*NRn];       // 67 MB
__device__ float g_O[BHn*Sn*HDn];

// ============================================================================
// Kernel 1: QKV projection.  C = A @ W, split to head-major layout.
// z=0: Q=query@Wq (scaled 1/8), z=1: K=value@Wk, z=2: V=value@Wv
// ============================================================================
__global__ __launch_bounds__(256)
void proj_kernel(const float* __restrict__ query,
                 const float* __restrict__ value,
                 const float* __restrict__ Wq,
                 const float* __restrict__ Wk,
                 const float* __restrict__ Wv)
{
    int t = blockIdx.z;
    const float* A = (t == 0) ? query : value;
    const float* W = (t == 0) ? Wq : (t == 1 ? Wk : Wv);
    float* Cdst    = (t == 0) ? g_Q : (t == 1 ? g_K : g_V);
    const float scale = (t == 0) ? 0.125f : 1.0f;

    __shared__ float As[32][68];   // [k][m], padded rows (272B, 16B aligned)
    __shared__ float Bs[32][68];   // [k][n]

    int m0 = blockIdx.y * 64;
    int n0 = blockIdx.x * 64;
    int tid = threadIdx.x;
    int tx = tid & 15;   // n group
    int ty = tid >> 4;   // m group

    float acc[4][4] = {};

    for (int k0 = 0; k0 < DMn; k0 += 32) {
        for (int i = tid; i < 64*32; i += 256) {
            int m = i >> 5, k = i & 31;
            As[k][m] = A[(size_t)(m0 + m)*DMn + k0 + k];
        }
        for (int i = tid; i < 32*64; i += 256) {
            int k = i >> 6, n = i & 63;
            Bs[k][n] = W[(size_t)(k0 + k)*DMn + n0 + n];
        }
        __syncthreads();
        #pragma unroll
        for (int kk = 0; kk < 32; kk++) {
            float av[4], bv[4];
            *(float4*)av = *(const float4*)&As[kk][ty*4];
            *(float4*)bv = *(const float4*)&Bs[kk][tx*4];
            #pragma unroll
            for (int i = 0; i < 4; i++)
                #pragma unroll
                for (int j = 0; j < 4; j++)
                    acc[i][j] += av[i]*bv[j];
        }
        __syncthreads();
    }

    #pragma unroll
    for (int i = 0; i < 4; i++) {
        int row = m0 + ty*4 + i;
        int b = row / Sn, s = row % Sn;
        #pragma unroll
        for (int j = 0; j < 4; j++) {
            int col = n0 + tx*4 + j;
            int h = col >> 6, d = col & 63;
            Cdst[(((size_t)(b*Hn + h))*Sn + s)*HDn + d] = acc[i][j]*scale;
        }
    }
}

// ============================================================================
// Kernel 2: REL[bh][s][r] = Qscaled[bh][s][:] . Ek[r][:]   (K=64)
// ============================================================================
__global__ __launch_bounds__(256)
void rel_kernel(const float* __restrict__ Ek)
{
    __shared__ float Qs[HDn][68];  // [d][s_local]
    __shared__ float Es[HDn][68];  // [d][r_local]

    int bh = blockIdx.z;
    int s0 = blockIdx.y * 64;
    int r0 = blockIdx.x * 64;
    int tid = threadIdx.x;

    for (int idx = tid; idx < 64*64; idx += 256) {
        int s = idx >> 6, d = idx & 63;
        Qs[d][s] = g_Q[((size_t)bh*Sn + s0 + s)*HDn + d];
    }
    for (int idx = tid; idx < 64*64; idx += 256) {
        int r = idx >> 6, d = idx & 63;
        Es[d][r] = (r0 + r < NRn) ? Ek[(size_t)(r0 + r)*HDn + d] : 0.f;
    }
    __syncthreads();

    int tx = tid & 15, ty = tid >> 4;
    float acc[4][4] = {};
    #pragma unroll 8
    for (int d = 0; d < 64; d++) {
        float av[4], bv[4];
        *(float4*)av = *(const float4*)&Qs[d][ty*4];
        *(float4*)bv = *(const float4*)&Es[d][tx*4];
        #pragma unroll
        for (int i = 0; i < 4; i++)
            #pragma unroll
            for (int j = 0; j < 4; j++)
                acc[i][j] += av[i]*bv[j];
    }

    #pragma unroll
    for (int i = 0; i < 4; i++) {
        int s = s0 + ty*4 + i;
        #pragma unroll
        for (int j = 0; j < 4; j++) {
            int r = r0 + tx*4 + j;
            if (r < NRn)
                g_REL[((size_t)bh*Sn + s)*NRn + r] = acc[i][j];
        }
    }
}

// ============================================================================
// Kernel 3: fused attention.  One CTA = 16 query rows of one (b,h).
//  alpha(16x2048) kept in smem -> exact softmax -> write attn_weights
//  -> bucket-sum W(16x513) -> O = P@V + W@Ev
// ============================================================================
struct AttnSmem {
    float A[BI][Sn];        // 131072 B : alpha -> p (normalized)
    float KV[8448];         // 33792 B  : K transposed (64 x 132) or V/Ev (128 x 64)
    float Q[BI][HDn];       // 4096 B
    float W[BI][NRn];       // 32832 B  : bucket sums
    float rsum[BI];         // 64 B
};

__global__ __launch_bounds__(256)
void attn_kernel(const float* __restrict__ Ev,
                 float* __restrict__ attn_out,
                 int write_attn)
{
    extern __shared__ char smem_raw[];
    AttnSmem& sm = *reinterpret_cast<AttnSmem*>(smem_raw);

    const int bh = blockIdx.y;
    const int i0 = blockIdx.x * BI;
    const int tid  = threadIdx.x;
    const int lane = tid & 31;
    const int warp = tid >> 5;

    // ---- load Q tile (16x64 contiguous floats) ----
    {
        const float4* src = reinterpret_cast<const float4*>(g_Q + ((size_t)bh*Sn + i0)*HDn);
        reinterpret_cast<float4*>(&sm.Q[0][0])[tid] = src[tid];
    }
    __syncthreads();

    // ---- alpha = Qs @ K^T + REL gather (Q pre-scaled by 1/8) ----
    const float* relRow = g_REL + ((size_t)bh*Sn + i0)*NRn;
    const int KSTRIDE = BJ + 4;           // 132: padded transposed K rows
    const int tx  = tid & 31;             // j group of 4
    const int ii0 = (tid >> 5) * 2;       // warp -> 2 rows

    for (int jc = 0; jc < Sn; jc += BJ) {
        for (int idx = tid; idx < BJ*HDn; idx += 256) {
            int j = idx >> 6, d = idx & 63;
            sm.KV[d*KSTRIDE + j] = g_K[((size_t)bh*Sn + jc + j)*HDn + d];
        }
        __syncthreads();

        float acc[2][4] = {};
        #pragma unroll 8
        for (int d = 0; d < HDn; d++) {
            float q0 = sm.Q[ii0][d];
            float q1 = sm.Q[ii0+1][d];
            float4 kv = *reinterpret_cast<const float4*>(&sm.KV[d*KSTRIDE + tx*4]);
            acc[0][0] += q0*kv.x; acc[0][1] += q0*kv.y; acc[0][2] += q0*kv.z; acc[0][3] += q0*kv.w;
            acc[1][0] += q1*kv.x; acc[1][1] += q1*kv.y; acc[1][2] += q1*kv.z; acc[1][3] += q1*kv.w;
        }
        #pragma unroll
        for (int r = 0; r < 2; r++) {
            int ii = ii0 + r;
            int i  = i0 + ii;
            #pragma unroll
            for (int c = 0; c < 4; c++) {
                int j = jc + tx*4 + c;
                int rel = j - i;
                rel = max(-256, min(256, rel));
                acc[r][c] += relRow[(size_t)ii*NRn + rel + 256];
            }
            float4 v = make_float4(acc[r][0], acc[r][1], acc[r][2], acc[r][3]);
            *reinterpret_cast<float4*>(&sm.A[ii][jc + tx*4]) = v;
        }
        __syncthreads();
    }

    // ---- softmax: each warp owns 2 rows ----
    #pragma unroll
    for (int r = 0; r < 2; r++) {
        int ii = warp*2 + r;
        float m = -1e30f;
        for (int j = lane; j < Sn; j += 32) m = fmaxf(m, sm.A[ii][j]);
        #pragma unroll
        for (int o = 16; o; o >>= 1) m = fmaxf(m, __shfl_xor_sync(0xFFFFFFFFu, m, o));
        float ssum = 0.f;
        for (int j = lane; j < Sn; j += 32) {
            float p = __expf(sm.A[ii][j] - m);
            sm.A[ii][j] = p;
            ssum += p;
        }
        #pragma unroll
        for (int o = 16; o; o >>= 1) ssum += __shfl_xor_sync(0xFFFFFFFFu, ssum, o);
        if (lane == 0) sm.rsum[ii] = ssum;
    }
    __syncthreads();

    // ---- normalize in smem and write attn_weights ----
    {
        float4* A4 = reinterpret_cast<float4*>(&sm.A[0][0]);
        for (int idx = tid; idx < BI*(Sn/4); idx += 256) {
            int ii = idx >> 9;                 // / (Sn/4)
            float inv = 1.0f / sm.rsum[ii];
            float4 v = A4[idx];
            v.x *= inv; v.y *= inv; v.z *= inv; v.w *= inv;
            A4[idx] = v;
            if (write_attn) {
                reinterpret_cast<float4*>(attn_out + ((size_t)bh*Sn + i0 + ii)*Sn)[idx & 511] = v;
            }
        }
    }
    __syncthreads();

    // ---- bucket sums W[ii][r] ----
    for (int idx = tid; idx < BI*511; idx += 256) {
        int ii = idx / 511;
        int r  = idx % 511 + 1;                // interior buckets: single j
        int j  = i0 + ii + r - 256;
        sm.W[ii][r] = (j >= 0 && j < Sn) ? sm.A[ii][j] : 0.f;
    }
    #pragma unroll
    for (int rr = 0; rr < 2; rr++) {
        int ii = warp*2 + rr;
        int i  = i0 + ii;
        float s0 = 0.f, s1 = 0.f;
        for (int j = lane; j <= i - 256; j += 32) s0 += sm.A[ii][j];       // r = 0 (clipped left)
        for (int j = i + 256 + lane; j < Sn; j += 32) s1 += sm.A[ii][j];   // r = 512 (clipped right)
        #pragma unroll
        for (int o = 16; o; o >>= 1) {
            s0 += __shfl_xor_sync(0xFFFFFFFFu, s0, o);
            s1 += __shfl_xor_sync(0xFFFFFFFFu, s1, o);
        }
        if (lane == 0) { sm.W[ii][0] = s0; sm.W[ii][512] = s1; }
    }
    __syncthreads();

    // ---- O = [P | W] @ [V ; Ev]  (concatenated j dim = 2048 + 513) ----
    const int dg = tid & 15;     // float4 column group
    const int oi = tid >> 4;     // output row 0..15
    float4 acc = make_float4(0.f, 0.f, 0.f, 0.f);
    const int TOT = Sn + NRn;    // 2561

    for (int jc = 0; jc < TOT; jc += BJ) {
        int rows = min(BJ, TOT - jc);
        for (int idx = tid; idx < rows*(HDn/4); idx += 256) {
            int q  = idx >> 4;
            int dq = idx & 15;
            int jr = jc + q;
            const float* src = (jr < Sn)
                ? (g_V + ((size_t)bh*Sn + jr)*HDn)
                : (Ev + (size_t)(jr - Sn)*HDn);
            reinterpret_cast<float4*>(&sm.KV[q*HDn])[dq] =
                reinterpret_cast<const float4*>(src)[dq];
        }
        __syncthreads();

        if (jc < Sn) {
            #pragma unroll 4
            for (int jj = 0; jj < BJ; jj++) {
                float w = sm.A[oi][jc + jj];
                float4 v = *reinterpret_cast<const float4*>(&sm.KV[jj*HDn + dg*4]);
                acc.x += w*v.x; acc.y += w*v.y; acc.z += w*v.z; acc.w += w*v.w;
            }
        } else {
            for (int jj = 0; jj < rows; jj++) {
                float w = sm.W[oi][jc - Sn + jj];
                float4 v = *reinterpret_cast<const float4*>(&sm.KV[jj*HDn + dg*4]);
                acc.x += w*v.x; acc.y += w*v.y; acc.z += w*v.z; acc.w += w*v.w;
            }
        }
        __syncthreads();
    }

    reinterpret_cast<float4*>(g_O + ((size_t)bh*Sn + i0 + oi)*HDn)[dg] = acc;
}

// ============================================================================
// Kernel 4: out = concat(O) @ Wo + bo
// ============================================================================
__global__ __launch_bounds__(256)
void outproj_kernel(const float* __restrict__ Wo,
                    const float* __restrict__ bo,
                    float* __restrict__ out)
{
    __shared__ float As[32][68];
    __shared__ float Bs[32][68];

    int m0 = blockIdx.y * 64;
    int n0 = blockIdx.x * 64;
    int tid = threadIdx.x;
    int tx = tid & 15, ty = tid >> 4;

    float acc[4][4] = {};

    for (int k0 = 0; k0 < DMn; k0 += 32) {
        for (int i = tid; i < 64*32; i += 256) {
            int m = i >> 5, k = i & 31;
            int row = m0 + m;
            int b = row / Sn, s = row % Sn;
            int c = k0 + k;
            int h = c >> 6, d = c & 63;
            As[k][m] = g_O[(((size_t)(b*Hn + h))*Sn + s)*HDn + d];
        }
        for (int i = tid; i < 32*64; i += 256) {
            int k = i >> 6, n = i & 63;
            Bs[k][n] = Wo[(size_t)(k0 + k)*DMn + n0 + n];
        }
        __syncthreads();
        #pragma unroll
        for (int kk = 0; kk < 32; kk++) {
            float av[4], bv[4];
            *(float4*)av = *(const float4*)&As[kk][ty*4];
            *(float4*)bv = *(const float4*)&Bs[kk][tx*4];
            #pragma unroll
            for (int i = 0; i < 4; i++)
                #pragma unroll
                for (int j = 0; j < 4; j++)
                    acc[i][j] += av[i]*bv[j];
        }
        __syncthreads();
    }

    #pragma unroll
    for (int i = 0; i < 4; i++) {
        int row = m0 + ty*4 + i;
        #pragma unroll
        for (int j = 0; j < 4; j++) {
            int col = n0 + tx*4 + j;
            out[(size_t)row*DMn + col] = acc[i][j] + bo[col];
        }
    }
}

// ============================================================================
extern "C" void kernel_launch(void* const* d_in, const int* in_sizes, int n_in,
                              void* d_out, int out_size)
{
    const float* query = (const float*)d_in[0];
    const float* value = (const float*)d_in[1];
    const float* Wq    = (const float*)d_in[2];
    const float* Wk    = (const float*)d_in[3];
    const float* Wv    = (const float*)d_in[4];
    const float* Wo    = (const float*)d_in[5];
    const float* bo    = (const float*)d_in[6];
    const float* Ek    = (const float*)d_in[7];
    const float* Ev    = (const float*)d_in[8];
    float* out = (float*)d_out;

    const int OUT_ELEMS  = Bn*Sn*DMn;                 // 2,097,152
    const long long FULL = (long long)OUT_ELEMS + (long long)BHn*Sn*Sn;
    int write_attn = ((long long)out_size >= FULL) ? 1 : 0;
    float* attn_out = out + (size_t)OUT_ELEMS;

    // QKV projections
    dim3 pg(DMn/64, (Bn*Sn)/64, 3);
    proj_kernel<<<pg, 256>>>(query, value, Wq, Wk, Wv);

    // relative-position logits
    dim3 rg((NRn + 63)/64, Sn/64, BHn);
    rel_kernel<<<rg, 256>>>(Ek);

    // fused attention
    cudaFuncSetAttribute(attn_kernel, cudaFuncAttributeMaxDynamicSharedMemorySize,
                         (int)sizeof(AttnSmem));
    dim3 ag(Sn/BI, BHn);
    attn_kernel<<<ag, 256, sizeof(AttnSmem)>>>(Ev, attn_out, write_attn);

    // output projection
    dim3 og(DMn/64, (Bn*Sn)/64);
    outproj_kernel<<<og, 256>>>(Wo, bo, out);
}

// round 3
// speedup vs baseline: 1.1203x; 1.1203x over previous
#include <cuda_runtime.h>

#define Bn   2
#define Sn   2048
#define Hn   8
#define DMn  512
#define HDn  64
#define NRn  513
#define BHn  (Bn*Hn)

#define BI   16     // query rows per attention CTA
#define BJ   128    // key/value/rel chunk
#define KS   130    // padded stride for transposed K/Ek tile (8B aligned, 2-way store conflict)
#define WS   520    // padded stride for W/relW rows (16B aligned)

// ---------------- scratch ----------------
__device__ float g_Q[BHn*Sn*HDn];                 // pre-scaled by 1/8
__device__ float g_K[BHn*Sn*HDn];
__device__ float g_V[BHn*Sn*HDn];
__device__ float g_O[BHn*Sn*HDn];

// ============================================================================
// Kernel 1: QKV projection.  C = A @ W, split to head-major layout.
// ============================================================================
__global__ __launch_bounds__(256)
void proj_kernel(const float* __restrict__ query,
                 const float* __restrict__ value,
                 const float* __restrict__ Wq,
                 const float* __restrict__ Wk,
                 const float* __restrict__ Wv)
{
    int t = blockIdx.z;
    const float* A = (t == 0) ? query : value;
    const float* W = (t == 0) ? Wq : (t == 1 ? Wk : Wv);
    float* Cdst    = (t == 0) ? g_Q : (t == 1 ? g_K : g_V);
    const float scale = (t == 0) ? 0.125f : 1.0f;

    __shared__ float As[32][68];
    __shared__ float Bs[32][68];

    int m0 = blockIdx.y * 64;
    int n0 = blockIdx.x * 64;
    int tid = threadIdx.x;
    int tx = tid & 15;
    int ty = tid >> 4;

    float acc[4][4] = {};

    for (int k0 = 0; k0 < DMn; k0 += 32) {
        for (int i = tid; i < 64*32; i += 256) {
            int m = i >> 5, k = i & 31;
            As[k][m] = A[(size_t)(m0 + m)*DMn + k0 + k];
        }
        for (int i = tid; i < 32*64; i += 256) {
            int k = i >> 6, n = i & 63;
            Bs[k][n] = W[(size_t)(k0 + k)*DMn + n0 + n];
        }
        __syncthreads();
        #pragma unroll
        for (int kk = 0; kk < 32; kk++) {
            float av[4], bv[4];
            *(float4*)av = *(const float4*)&As[kk][ty*4];
            *(float4*)bv = *(const float4*)&Bs[kk][tx*4];
            #pragma unroll
            for (int i = 0; i < 4; i++)
                #pragma unroll
                for (int j = 0; j < 4; j++)
                    acc[i][j] += av[i]*bv[j];
        }
        __syncthreads();
    }

    #pragma unroll
    for (int i = 0; i < 4; i++) {
        int row = m0 + ty*4 + i;
        int b = row / Sn, s = row % Sn;
        #pragma unroll
        for (int j = 0; j < 4; j++) {
            int col = n0 + tx*4 + j;
            int h = col >> 6, d = col & 63;
            Cdst[(((size_t)(b*Hn + h))*Sn + s)*HDn + d] = acc[i][j]*scale;
        }
    }
}

// ============================================================================
// Kernel 2: fused attention. One CTA = 16 query rows of one (b,h).
//   relW(16x513) computed in-kernel -> alpha(16x2048) in smem -> exact softmax
//   -> write attn_weights -> bucket-sum W(16x513) -> O = P@V + W@Ev
// ============================================================================
struct AttnSmem {
    float A[BI][Sn];         // 131072 B : alpha -> p (normalized)
    float Kt[HDn*KS];        // 33280 B  : K^T / Ek^T (64 x 130) | V/Ev chunk (128x64) | reduce buf
    float Qt[HDn][BI];       // 4096 B   : Q^T
    float W[BI][WS];         // 33280 B  : relW, then bucket sums
    float rsum[BI];          // 64 B
};

__global__ __launch_bounds__(256)
void attn_kernel(const float* __restrict__ Ek,
                 const float* __restrict__ Ev,
                 float* __restrict__ attn_out,
                 int write_attn)
{
    extern __shared__ char smem_raw[];
    AttnSmem& sm = *reinterpret_cast<AttnSmem*>(smem_raw);

    const int bh = blockIdx.y;
    const int i0 = blockIdx.x * BI;
    const int tid  = threadIdx.x;
    const int lane = tid & 31;
    const int warp = tid >> 5;

    // GEMM-phase thread tile: 4 rows x 2 cols
    const int ty = tid >> 6;      // 0..3 -> rows ty*4..ty*4+3
    const int tx = tid & 63;      // 0..63 -> cols tx*2, tx*2+1

    // ---- load Q^T tile (Qt[d][ii]) ----
    for (int idx = tid; idx < BI*HDn; idx += 256) {
        int ii = idx >> 6, d = idx & 63;
        sm.Qt[d][ii] = g_Q[((size_t)bh*Sn + i0 + ii)*HDn + d];
    }

    // ---- REL phase: relW[ii][r] = Qs . Ek[r]  (into sm.W) ----
    for (int r0 = 0; r0 < NRn; r0 += BJ) {
        int rcnt = min(BJ, NRn - r0);
        for (int idx = tid; idx < BJ*HDn; idx += 256) {
            int r = idx >> 6, d = idx & 63;
            sm.Kt[d*KS + r] = (r < rcnt) ? Ek[(size_t)(r0 + r)*HDn + d] : 0.f;
        }
        __syncthreads();

        float acc[4][2] = {};
        #pragma unroll 8
        for (int d = 0; d < HDn; d++) {
            float4 qv = *(const float4*)&sm.Qt[d][ty*4];
            float2 kv = *(const float2*)&sm.Kt[d*KS + tx*2];
            acc[0][0] += qv.x*kv.x; acc[0][1] += qv.x*kv.y;
            acc[1][0] += qv.y*kv.x; acc[1][1] += qv.y*kv.y;
            acc[2][0] += qv.z*kv.x; acc[2][1] += qv.z*kv.y;
            acc[3][0] += qv.w*kv.x; acc[3][1] += qv.w*kv.y;
        }
        #pragma unroll
        for (int i = 0; i < 4; i++) {
            #pragma unroll
            for (int c = 0; c < 2; c++) {
                int r = tx*2 + c;
                if (r < rcnt) sm.W[ty*4 + i][r0 + r] = acc[i][c];
            }
        }
        __syncthreads();
    }

    // ---- alpha = Qs @ K^T + relW gather ----
    for (int jc = 0; jc < Sn; jc += BJ) {
        for (int idx = tid; idx < BJ*HDn; idx += 256) {
            int j = idx >> 6, d = idx & 63;
            sm.Kt[d*KS + j] = g_K[((size_t)bh*Sn + jc + j)*HDn + d];
        }
        __syncthreads();

        float acc[4][2] = {};
        #pragma unroll 8
        for (int d = 0; d < HDn; d++) {
            float4 qv = *(const float4*)&sm.Qt[d][ty*4];
            float2 kv = *(const float2*)&sm.Kt[d*KS + tx*2];
            acc[0][0] += qv.x*kv.x; acc[0][1] += qv.x*kv.y;
            acc[1][0] += qv.y*kv.x; acc[1][1] += qv.y*kv.y;
            acc[2][0] += qv.z*kv.x; acc[2][1] += qv.z*kv.y;
            acc[3][0] += qv.w*kv.x; acc[3][1] += qv.w*kv.y;
        }
        #pragma unroll
        for (int i = 0; i < 4; i++) {
            int ii = ty*4 + i;
            int gi = i0 + ii;
            #pragma unroll
            for (int c = 0; c < 2; c++) {
                int j = jc + tx*2 + c;
                int rel = min(256, max(-256, j - gi)) + 256;
                sm.A[ii][j] = acc[i][c] + sm.W[ii][rel];
            }
        }
        __syncthreads();
    }

    // ---- softmax: each warp owns 2 rows ----
    #pragma unroll
    for (int r = 0; r < 2; r++) {
        int ii = warp*2 + r;
        float m = -1e30f;
        for (int j = lane; j < Sn; j += 32) m = fmaxf(m, sm.A[ii][j]);
        #pragma unroll
        for (int o = 16; o; o >>= 1) m = fmaxf(m, __shfl_xor_sync(0xFFFFFFFFu, m, o));
        float ssum = 0.f;
        for (int j = lane; j < Sn; j += 32) {
            float p = __expf(sm.A[ii][j] - m);
            sm.A[ii][j] = p;
            ssum += p;
        }
        #pragma unroll
        for (int o = 16; o; o >>= 1) ssum += __shfl_xor_sync(0xFFFFFFFFu, ssum, o);
        if (lane == 0) sm.rsum[ii] = ssum;
    }
    __syncthreads();

    // ---- normalize in smem and write attn_weights ----
    {
        float4* A4 = reinterpret_cast<float4*>(&sm.A[0][0]);
        for (int idx = tid; idx < BI*(Sn/4); idx += 256) {
            int ii = idx >> 9;
            float inv = 1.0f / sm.rsum[ii];
            float4 v = A4[idx];
            v.x *= inv; v.y *= inv; v.z *= inv; v.w *= inv;
            A4[idx] = v;
            if (write_attn) {
                reinterpret_cast<float4*>(attn_out + ((size_t)bh*Sn + i0 + ii)*Sn)[idx & 511] = v;
            }
        }
    }
    __syncthreads();

    // ---- bucket sums W[ii][r] (overwrites relW) ----
    for (int idx = tid; idx < BI*511; idx += 256) {
        int ii = idx / 511;
        int r  = idx % 511 + 1;
        int j  = i0 + ii + r - 256;
        sm.W[ii][r] = (j >= 0 && j < Sn) ? sm.A[ii][j] : 0.f;
    }
    #pragma unroll
    for (int rr = 0; rr < 2; rr++) {
        int ii = warp*2 + rr;
        int i  = i0 + ii;
        float s0 = 0.f, s1 = 0.f;
        for (int j = lane; j <= i - 256; j += 32) s0 += sm.A[ii][j];
        for (int j = i + 256 + lane; j < Sn; j += 32) s1 += sm.A[ii][j];
        #pragma unroll
        for (int o = 16; o; o >>= 1) {
            s0 += __shfl_xor_sync(0xFFFFFFFFu, s0, o);
            s1 += __shfl_xor_sync(0xFFFFFFFFu, s1, o);
        }
        if (lane == 0) { sm.W[ii][0] = s0; sm.W[ii][512] = s1; }
    }
    __syncthreads();

    // ---- O = [P | W] @ [V ; Ev] with 4-way j-split register tiling ----
    const int g   = tid >> 6;       // j-split group 0..3
    const int tg  = tid & 63;
    const int tyo = tg >> 4;        // rows tyo*4..+3
    const int txo = tg & 15;        // cols txo*4..+3
    const int TOT = Sn + NRn;       // 2561

    float acc[4][4] = {};

    for (int jc = 0; jc < TOT; jc += BJ) {
        int rows = min(BJ, TOT - jc);
        for (int idx = tid; idx < rows*(HDn/4); idx += 256) {
            int q = idx >> 4, dq = idx & 15;
            int jr = jc + q;
            const float* src = (jr < Sn)
                ? (g_V + ((size_t)bh*Sn + jr)*HDn)
                : (Ev + (size_t)(jr - Sn)*HDn);
            reinterpret_cast<float4*>(&sm.Kt[q*HDn])[dq] =
                reinterpret_cast<const float4*>(src)[dq];
        }
        __syncthreads();

        const bool useA = (jc < Sn);
        const int base  = useA ? jc : jc - Sn;
        int jbeg = g*32;
        int jend = min(jbeg + 32, rows);

        if (jbeg < jend) {
            int jvec_end = jbeg + ((jend - jbeg) & ~3);
            for (int j4 = jbeg; j4 < jvec_end; j4 += 4) {
                float4 w[4], v[4];
                #pragma unroll
                for (int i = 0; i < 4; i++)
                    w[i] = useA ? *(const float4*)&sm.A[tyo*4 + i][base + j4]
                                : *(const float4*)&sm.W[tyo*4 + i][base + j4];
                #pragma unroll
                for (int q = 0; q < 4; q++)
                    v[q] = *(const float4*)&sm.Kt[(j4 + q)*HDn + txo*4];
                #pragma unroll
                for (int i = 0; i < 4; i++) {
                    acc[i][0] += w[i].x*v[0].x + w[i].y*v[1].x + w[i].z*v[2].x + w[i].w*v[3].x;
                    acc[i][1] += w[i].x*v[0].y + w[i].y*v[1].y + w[i].z*v[2].y + w[i].w*v[3].y;
                    acc[i][2] += w[i].x*v[0].z + w[i].y*v[1].z + w[i].z*v[2].z + w[i].w*v[3].z;
                    acc[i][3] += w[i].x*v[0].w + w[i].y*v[1].w + w[i].z*v[2].w + w[i].w*v[3].w;
                }
            }
            for (int j = jvec_end; j < jend; j++) {
                float4 vv = *(const float4*)&sm.Kt[j*HDn + txo*4];
                #pragma unroll
                for (int i = 0; i < 4; i++) {
                    float wv = useA ? sm.A[tyo*4 + i][base + j]
                                    : sm.W[tyo*4 + i][base + j];
                    acc[i][0] += wv*vv.x; acc[i][1] += wv*vv.y;
                    acc[i][2] += wv*vv.z; acc[i][3] += wv*vv.w;
                }
            }
        }
        __syncthreads();
    }

    // ---- reduce 4 partial groups through Kt buffer, write O ----
    #pragma unroll
    for (int i = 0; i < 4; i++) {
        int ii = tyo*4 + i;
        *(float4*)&sm.Kt[((size_t)g*16 + ii)*HDn + txo*4] =
            make_float4(acc[i][0], acc[i][1], acc[i][2], acc[i][3]);
    }
    __syncthreads();
    for (int idx = tid; idx < BI*HDn; idx += 256) {
        int ii = idx >> 6, d = idx & 63;
        float s = sm.Kt[(size_t)ii*HDn + d]
                + sm.Kt[((size_t)16 + ii)*HDn + d]
                + sm.Kt[((size_t)32 + ii)*HDn + d]
                + sm.Kt[((size_t)48 + ii)*HDn + d];
        g_O[((size_t)bh*Sn + i0 + ii)*HDn + d] = s;
    }
}

// ============================================================================
// Kernel 3: out = concat(O) @ Wo + bo
// ============================================================================
__global__ __launch_bounds__(256)
void outproj_kernel(const float* __restrict__ Wo,
                    const float* __restrict__ bo,
                    float* __restrict__ out)
{
    __shared__ float As[32][68];
    __shared__ float Bs[32][68];

    int m0 = blockIdx.y * 64;
    int n0 = blockIdx.x * 64;
    int tid = threadIdx.x;
    int tx = tid & 15, ty = tid >> 4;

    float acc[4][4] = {};

    for (int k0 = 0; k0 < DMn; k0 += 32) {
        for (int i = tid; i < 64*32; i += 256) {
            int m = i >> 5, k = i & 31;
            int row = m0 + m;
            int b = row / Sn, s = row % Sn;
            int c = k0 + k;
            int h = c >> 6, d = c & 63;
            As[k][m] = g_O[(((size_t)(b*Hn + h))*Sn + s)*HDn + d];
        }
        for (int i = tid; i < 32*64; i += 256) {
            int k = i >> 6, n = i & 63;
            Bs[k][n] = Wo[(size_t)(k0 + k)*DMn + n0 + n];
        }
        __syncthreads();
        #pragma unroll
        for (int kk = 0; kk < 32; kk++) {
            float av[4], bv[4];
            *(float4*)av = *(const float4*)&As[kk][ty*4];
            *(float4*)bv = *(const float4*)&Bs[kk][tx*4];
            #pragma unroll
            for (int i = 0; i < 4; i++)
                #pragma unroll
                for (int j = 0; j < 4; j++)
                    acc[i][j] += av[i]*bv[j];
        }
        __syncthreads();
    }

    #pragma unroll
    for (int i = 0; i < 4; i++) {
        int row = m0 + ty*4 + i;
        #pragma unroll
        for (int j = 0; j < 4; j++) {
            int col = n0 + tx*4 + j;
            out[(size_t)row*DMn + col] = acc[i][j] + bo[col];
        }
    }
}

// ============================================================================
extern "C" void kernel_launch(void* const* d_in, const int* in_sizes, int n_in,
                              void* d_out, int out_size)
{
    const float* query = (const float*)d_in[0];
    const float* value = (const float*)d_in[1];
    const float* Wq    = (const float*)d_in[2];
    const float* Wk    = (const float*)d_in[3];
    const float* Wv    = (const float*)d_in[4];
    const float* Wo    = (const float*)d_in[5];
    const float* bo    = (const float*)d_in[6];
    const float* Ek    = (const float*)d_in[7];
    const float* Ev    = (const float*)d_in[8];
    float* out = (float*)d_out;

    const int OUT_ELEMS  = Bn*Sn*DMn;
    const long long FULL = (long long)OUT_ELEMS + (long long)BHn*Sn*Sn;
    int write_attn = ((long long)out_size >= FULL) ? 1 : 0;
    float* attn_out = out + (size_t)OUT_ELEMS;

    // QKV projections
    dim3 pg(DMn/64, (Bn*Sn)/64, 3);
    proj_kernel<<<pg, 256>>>(query, value, Wq, Wk, Wv);

    // fused attention (REL computed in-kernel)
    cudaFuncSetAttribute(attn_kernel, cudaFuncAttributeMaxDynamicSharedMemorySize,
                         (int)sizeof(AttnSmem));
    dim3 ag(Sn/BI, BHn);
    attn_kernel<<<ag, 256, sizeof(AttnSmem)>>>(Ek, Ev, attn_out, write_attn);

    // output projection
    dim3 og(DMn/64, (Bn*Sn)/64);
    outproj_kernel<<<og, 256>>>(Wo, bo, out);
}

// round 5
// speedup vs baseline: 1.7146x; 1.5304x over previous
#include <cuda_runtime.h>
#include <cuda_bf16.h>
#include <cstdint>

#define Bn   2
#define Sn   2048
#define Hn   8
#define DMn  512
#define HDn  64
#define NRn  513
#define BHn  (Bn*Hn)
#define WBS  576     // padded stride for Wb / EvT

// ---------------- fp32 scratch ----------------
__device__ float g_Q[BHn*Sn*HDn];          // pre-scaled by 1/8
__device__ float g_K[BHn*Sn*HDn];
__device__ float g_V[BHn*Sn*HDn];
__device__ float g_O[BHn*Sn*HDn];
__device__ float g_Wb[(size_t)BHn*Sn*WBS]; // bucket sums, zero padded

// ---------------- bf16 hi/lo scratch ----------------
__device__ __nv_bfloat16 g_Qh[BHn*Sn*HDn], g_Ql[BHn*Sn*HDn];
__device__ __nv_bfloat16 g_Kh[BHn*Sn*HDn], g_Kl[BHn*Sn*HDn];
__device__ __nv_bfloat16 g_VTh[BHn*HDn*Sn], g_VTl[BHn*HDn*Sn]; // [bh][d][s]
__device__ __nv_bfloat16 g_EvTh[HDn*WBS],  g_EvTl[HDn*WBS];    // [d][r]

// ============================================================================
// helpers
// ============================================================================
__device__ __forceinline__ uint32_t smem_u32(const void* p) {
    uint32_t a;
    asm("{ .reg .u64 t; cvta.to.shared.u64 t, %1; cvt.u32.u64 %0, t; }"
        : "=r"(a) : "l"(p));
    return a;
}

__device__ __forceinline__ void ldsm_x4(uint32_t& r0, uint32_t& r1,
                                        uint32_t& r2, uint32_t& r3,
                                        uint32_t addr) {
    asm volatile("ldmatrix.sync.aligned.m8n8.x4.shared.b16 {%0,%1,%2,%3}, [%4];"
                 : "=r"(r0), "=r"(r1), "=r"(r2), "=r"(r3) : "r"(addr));
}

__device__ __forceinline__ void mma16816(float* d, const uint32_t* a,
                                         uint32_t b0, uint32_t b1) {
    asm volatile(
        "mma.sync.aligned.m16n8k16.row.col.f32.bf16.bf16.f32 "
        "{%0,%1,%2,%3}, {%4,%5,%6,%7}, {%8,%9}, {%0,%1,%2,%3};"
        : "+f"(d[0]), "+f"(d[1]), "+f"(d[2]), "+f"(d[3])
        : "r"(a[0]), "r"(a[1]), "r"(a[2]), "r"(a[3]), "r"(b0), "r"(b1));
}

union B8 { __nv_bfloat16 b[8]; uint4 u; };
union B4 { __nv_bfloat16 b[4]; uint2 u; };

__device__ __forceinline__ void split1(float x, __nv_bfloat16& h, __nv_bfloat16& l) {
    h = __float2bfloat16(x);
    l = __float2bfloat16(x - __bfloat162float(h));
}

// ============================================================================
// Kernel: QKV projection (FFMA)
// ============================================================================
__global__ __launch_bounds__(256)
void proj_kernel(const float* __restrict__ query,
                 const float* __restrict__ value,
                 const float* __restrict__ Wq,
                 const float* __restrict__ Wk,
                 const float* __restrict__ Wv)
{
    int t = blockIdx.z;
    const float* A = (t == 0) ? query : value;
    const float* W = (t == 0) ? Wq : (t == 1 ? Wk : Wv);
    float* Cdst    = (t == 0) ? g_Q : (t == 1 ? g_K : g_V);
    const float scale = (t == 0) ? 0.125f : 1.0f;

    __shared__ float As[32][68];
    __shared__ float Bs[32][68];

    int m0 = blockIdx.y * 64;
    int n0 = blockIdx.x * 64;
    int tid = threadIdx.x;
    int tx = tid & 15, ty = tid >> 4;

    float acc[4][4] = {};
    for (int k0 = 0; k0 < DMn; k0 += 32) {
        for (int i = tid; i < 64*32; i += 256) {
            int m = i >> 5, k = i & 31;
            As[k][m] = A[(size_t)(m0 + m)*DMn + k0 + k];
        }
        for (int i = tid; i < 32*64; i += 256) {
            int k = i >> 6, n = i & 63;
            Bs[k][n] = W[(size_t)(k0 + k)*DMn + n0 + n];
        }
        __syncthreads();
        #pragma unroll
        for (int kk = 0; kk < 32; kk++) {
            float av[4], bv[4];
            *(float4*)av = *(const float4*)&As[kk][ty*4];
            *(float4*)bv = *(const float4*)&Bs[kk][tx*4];
            #pragma unroll
            for (int i = 0; i < 4; i++)
                #pragma unroll
                for (int j = 0; j < 4; j++)
                    acc[i][j] += av[i]*bv[j];
        }
        __syncthreads();
    }
    #pragma unroll
    for (int i = 0; i < 4; i++) {
        int row = m0 + ty*4 + i;
        int b = row / Sn, s = row % Sn;
        #pragma unroll
        for (int j = 0; j < 4; j++) {
            int col = n0 + tx*4 + j;
            int h = col >> 6, d = col & 63;
            Cdst[(((size_t)(b*Hn + h))*Sn + s)*HDn + d] = acc[i][j]*scale;
        }
    }
}

// ============================================================================
// Convert kernels
// ============================================================================
__global__ __launch_bounds__(256)
void conv_qk_kernel()
{
    const size_t N4 = (size_t)BHn*Sn*HDn/4;
    size_t stride = (size_t)gridDim.x*blockDim.x;
    for (size_t i = (size_t)blockIdx.x*blockDim.x + threadIdx.x; i < N4; i += stride) {
        float4 q = ((const float4*)g_Q)[i];
        B4 h, l;
        split1(q.x, h.b[0], l.b[0]); split1(q.y, h.b[1], l.b[1]);
        split1(q.z, h.b[2], l.b[2]); split1(q.w, h.b[3], l.b[3]);
        *(uint2*)&g_Qh[4*i] = h.u; *(uint2*)&g_Ql[4*i] = l.u;

        float4 k = ((const float4*)g_K)[i];
        split1(k.x, h.b[0], l.b[0]); split1(k.y, h.b[1], l.b[1]);
        split1(k.z, h.b[2], l.b[2]); split1(k.w, h.b[3], l.b[3]);
        *(uint2*)&g_Kh[4*i] = h.u; *(uint2*)&g_Kl[4*i] = l.u;
    }
}

__global__ __launch_bounds__(256)
void conv_vt_kernel()
{
    __shared__ float t[64][65];
    int bh = blockIdx.y;
    int s0 = blockIdx.x * 64;
    int tid = threadIdx.x;
    for (int idx = tid; idx < 64*64; idx += 256) {
        int r = idx >> 6, c = idx & 63;
        t[r][c] = g_V[((size_t)bh*Sn + s0 + r)*HDn + c];
    }
    __syncthreads();
    for (int idx = tid; idx < 64*64; idx += 256) {
        int d = idx >> 6, ss = idx & 63;
        __nv_bfloat16 h, l;
        split1(t[ss][d], h, l);
        size_t o = ((size_t)bh*HDn + d)*Sn + s0 + ss;
        g_VTh[o] = h; g_VTl[o] = l;
    }
}

__global__ __launch_bounds__(256)
void conv_ev_kernel(const float* __restrict__ Ev)
{
    int tid = threadIdx.x;
    for (int idx = tid; idx < HDn*WBS; idx += 256) {
        int d = idx / WBS, r = idx % WBS;
        float v = (r < NRn) ? Ev[(size_t)r*HDn + d] : 0.f;
        __nv_bfloat16 h, l;
        split1(v, h, l);
        g_EvTh[idx] = h; g_EvTl[idx] = l;
    }
}

// ============================================================================
// alpha kernel (mma.sync): alpha[128 x 128] = Q·K^T, bf16 3-term split
// ============================================================================
#define ASB 144                        // padded smem row stride (bytes) = 72 bf16
#define AK_QH 0
#define AK_QL (128*ASB)
#define AK_KH (2*128*ASB)
#define AK_KL (3*128*ASB)
#define AK_BYTES (4*128*ASB)           // 73728

__global__ __launch_bounds__(256)
void alpha_kernel(float* __restrict__ alpha_out)
{
    extern __shared__ char sm[];
    uint32_t sb = smem_u32(sm);
    const int tid  = threadIdx.x;
    const int lane = tid & 31;
    const int warp = tid >> 5;
    const int bh = blockIdx.z;
    const int i0 = blockIdx.y * 128;
    const int j0 = blockIdx.x * 128;

    // load Q/K hi+lo tiles (128 x 64 bf16 each)
    {
        const uint4* qh = (const uint4*)(g_Qh + ((size_t)bh*Sn + i0)*HDn);
        const uint4* ql = (const uint4*)(g_Ql + ((size_t)bh*Sn + i0)*HDn);
        const uint4* kh = (const uint4*)(g_Kh + ((size_t)bh*Sn + j0)*HDn);
        const uint4* kl = (const uint4*)(g_Kl + ((size_t)bh*Sn + j0)*HDn);
        for (int it = tid; it < 1024; it += 256) {
            int r = it >> 3, c = it & 7;
            int so = r*ASB + c*16;
            *(uint4*)(sm + AK_QH + so) = qh[it];
            *(uint4*)(sm + AK_QL + so) = ql[it];
            *(uint4*)(sm + AK_KH + so) = kh[it];
            *(uint4*)(sm + AK_KL + so) = kl[it];
        }
    }
    __syncthreads();

    const int m0 = (warp >> 2) * 64;   // 0 or 64
    const int n0 = (warp & 3) * 32;    // 0..96
    const uint32_t loff = (uint32_t)((lane & 15)*ASB + (lane >> 4)*16);

    float acc[4][4][4] = {};

    const uint32_t abase[3] = { sb + AK_QH, sb + AK_QH, sb + AK_QL };
    const uint32_t bbase[3] = { sb + AK_KH, sb + AK_KL, sb + AK_KH };

    #pragma unroll
    for (int t = 0; t < 3; t++) {
        #pragma unroll
        for (int kt = 0; kt < 4; kt++) {
            uint32_t koff = kt*32;
            uint32_t a[4][4];
            #pragma unroll
            for (int mi = 0; mi < 4; mi++)
                ldsm_x4(a[mi][0], a[mi][1], a[mi][2], a[mi][3],
                        abase[t] + (uint32_t)(m0 + mi*16)*ASB + koff + loff);
            uint32_t b[2][4];
            #pragma unroll
            for (int bi = 0; bi < 2; bi++)
                ldsm_x4(b[bi][0], b[bi][1], b[bi][2], b[bi][3],
                        bbase[t] + (uint32_t)(n0 + bi*16)*ASB + koff + loff);
            #pragma unroll
            for (int mi = 0; mi < 4; mi++) {
                mma16816(acc[mi][0], a[mi], b[0][0], b[0][2]);
                mma16816(acc[mi][1], a[mi], b[0][1], b[0][3]);
                mma16816(acc[mi][2], a[mi], b[1][0], b[1][2]);
                mma16816(acc[mi][3], a[mi], b[1][1], b[1][3]);
            }
        }
    }

    // write fragments directly (float2 per row-pair, 8B aligned)
    #pragma unroll
    for (int mi = 0; mi < 4; mi++) {
        int row = i0 + m0 + mi*16 + (lane >> 2);
        float* base0 = alpha_out + ((size_t)bh*Sn + row)*Sn + j0;
        float* base1 = base0 + 8*(size_t)Sn;
        #pragma unroll
        for (int ni = 0; ni < 4; ni++) {
            int col = n0 + ni*8 + (lane & 3)*2;
            *(float2*)(base0 + col) = make_float2(acc[mi][ni][0], acc[mi][ni][1]);
            *(float2*)(base1 + col) = make_float2(acc[mi][ni][2], acc[mi][ni][3]);
        }
    }
}

// ============================================================================
// softmax kernel: relW (FFMA) + alpha + exact softmax + write p + Wb
// ============================================================================
#define BI 16
#define KS 130
#define WS 520
struct SoftSmem {
    float A[BI][Sn];
    float Kt[HDn*KS];
    float Qt[HDn][BI];
    float W[BI][WS];
    float rsum[BI];
};

__global__ __launch_bounds__(256)
void softmax_kernel(const float* __restrict__ Ek,
                    float* __restrict__ attn)   // in: raw alpha, out: p
{
    extern __shared__ char smem_raw[];
    SoftSmem& sm = *reinterpret_cast<SoftSmem*>(smem_raw);

    const int bh = blockIdx.y;
    const int i0 = blockIdx.x * BI;
    const int tid  = threadIdx.x;
    const int lane = tid & 31;
    const int warp = tid >> 5;
    const int ty = tid >> 6;
    const int tx = tid & 63;

    for (int idx = tid; idx < BI*HDn; idx += 256) {
        int ii = idx >> 6, d = idx & 63;
        sm.Qt[d][ii] = g_Q[((size_t)bh*Sn + i0 + ii)*HDn + d];
    }

    for (int r0 = 0; r0 < NRn; r0 += 128) {
        int rcnt = min(128, NRn - r0);
        for (int idx = tid; idx < 128*HDn; idx += 256) {
            int r = idx >> 6, d = idx & 63;
            sm.Kt[d*KS + r] = (r < rcnt) ? Ek[(size_t)(r0 + r)*HDn + d] : 0.f;
        }
        __syncthreads();
        float acc[4][2] = {};
        #pragma unroll 8
        for (int d = 0; d < HDn; d++) {
            float4 qv = *(const float4*)&sm.Qt[d][ty*4];
            float2 kv = *(const float2*)&sm.Kt[d*KS + tx*2];
            acc[0][0] += qv.x*kv.x; acc[0][1] += qv.x*kv.y;
            acc[1][0] += qv.y*kv.x; acc[1][1] += qv.y*kv.y;
            acc[2][0] += qv.z*kv.x; acc[2][1] += qv.z*kv.y;
            acc[3][0] += qv.w*kv.x; acc[3][1] += qv.w*kv.y;
        }
        #pragma unroll
        for (int i = 0; i < 4; i++)
            #pragma unroll
            for (int c = 0; c < 2; c++) {
                int r = tx*2 + c;
                if (r < rcnt) sm.W[ty*4 + i][r0 + r] = acc[i][c];
            }
        __syncthreads();
    }

    {
        const float* araw = attn + ((size_t)bh*Sn + i0)*Sn;
        for (int idx = tid; idx < BI*(Sn/4); idx += 256) {
            int ii = idx >> 9;
            int j4 = (idx & 511)*4;
            float4 v = *(const float4*)(araw + (size_t)ii*Sn + j4);
            int i = i0 + ii;
            v.x += sm.W[ii][min(256, max(-256, j4     - i)) + 256];
            v.y += sm.W[ii][min(256, max(-256, j4 + 1 - i)) + 256];
            v.z += sm.W[ii][min(256, max(-256, j4 + 2 - i)) + 256];
            v.w += sm.W[ii][min(256, max(-256, j4 + 3 - i)) + 256];
            *(float4*)&sm.A[ii][j4] = v;
        }
    }
    __syncthreads();

    #pragma unroll
    for (int r = 0; r < 2; r++) {
        int ii = warp*2 + r;
        float m = -1e30f;
        for (int j = lane; j < Sn; j += 32) m = fmaxf(m, sm.A[ii][j]);
        #pragma unroll
        for (int o = 16; o; o >>= 1) m = fmaxf(m, __shfl_xor_sync(0xFFFFFFFFu, m, o));
        float ssum = 0.f;
        for (int j = lane; j < Sn; j += 32) {
            float p = __expf(sm.A[ii][j] - m);
            sm.A[ii][j] = p;
            ssum += p;
        }
        #pragma unroll
        for (int o = 16; o; o >>= 1) ssum += __shfl_xor_sync(0xFFFFFFFFu, ssum, o);
        if (lane == 0) sm.rsum[ii] = ssum;
    }
    __syncthreads();

    {
        float4* A4 = reinterpret_cast<float4*>(&sm.A[0][0]);
        for (int idx = tid; idx < BI*(Sn/4); idx += 256) {
            int ii = idx >> 9;
            float inv = 1.0f / sm.rsum[ii];
            float4 v = A4[idx];
            v.x *= inv; v.y *= inv; v.z *= inv; v.w *= inv;
            A4[idx] = v;
            reinterpret_cast<float4*>(attn + ((size_t)bh*Sn + i0 + ii)*Sn)[idx & 511] = v;
        }
    }
    __syncthreads();

    for (int idx = tid; idx < BI*511; idx += 256) {
        int ii = idx / 511;
        int r  = idx % 511 + 1;
        int j  = i0 + ii + r - 256;
        sm.W[ii][r] = (j >= 0 && j < Sn) ? sm.A[ii][j] : 0.f;
    }
    #pragma unroll
    for (int rr = 0; rr < 2; rr++) {
        int ii = warp*2 + rr;
        int i  = i0 + ii;
        float s0 = 0.f, s1 = 0.f;
        for (int j = lane; j <= i - 256; j += 32) s0 += sm.A[ii][j];
        for (int j = i + 256 + lane; j < Sn; j += 32) s1 += sm.A[ii][j];
        #pragma unroll
        for (int o = 16; o; o >>= 1) {
            s0 += __shfl_xor_sync(0xFFFFFFFFu, s0, o);
            s1 += __shfl_xor_sync(0xFFFFFFFFu, s1, o);
        }
        if (lane == 0) { sm.W[ii][0] = s0; sm.W[ii][512] = s1; }
    }
    __syncthreads();

    for (int idx = tid; idx < BI*WBS; idx += 256) {
        int ii = idx / WBS, r = idx % WBS;
        g_Wb[((size_t)bh*Sn + i0 + ii)*WBS + r] = (r < NRn) ? sm.W[ii][r] : 0.f;
    }
}

// ============================================================================
// pv kernel (mma.sync): O[128 x 64] = P·V + Wb·Ev, bf16 3-term split
// K streamed in 41 chunks of 64
// ============================================================================
#define PV_PH 0
#define PV_PL (128*ASB)
#define PV_VH (2*128*ASB)
#define PV_VL (2*128*ASB + 64*ASB)
#define PV_BYTES (2*128*ASB + 2*64*ASB)   // 55296

__global__ __launch_bounds__(256)
void pv_kernel(const float* __restrict__ attn)
{
    extern __shared__ char sm[];
    uint32_t sb = smem_u32(sm);
    const int tid  = threadIdx.x;
    const int lane = tid & 31;
    const int warp = tid >> 5;
    const int bh = blockIdx.y;
    const int i0 = blockIdx.x * 128;

    const int m0 = (warp >> 1) * 32;   // 0,32,64,96
    const int n0 = (warp & 1) * 32;    // 0,32
    const uint32_t loff = (uint32_t)((lane & 15)*ASB + (lane >> 4)*16);

    float acc[2][4][4] = {};

    const int NCHUNK = 32 + WBS/64;    // 41
    for (int s = 0; s < NCHUNK; s++) {
        // stage A: 128 rows x 64 fp32 -> hi/lo bf16
        {
            const float* Abase;
            size_t Astr;
            if (s < 32) { Abase = attn + ((size_t)bh*Sn + i0)*Sn + s*64;        Astr = Sn; }
            else        { Abase = g_Wb + ((size_t)bh*Sn + i0)*WBS + (s-32)*64;  Astr = WBS; }
            for (int it = tid; it < 2048; it += 256) {
                int r = it >> 4, c4 = it & 15;   // c4*4 floats
                float4 v = *(const float4*)(Abase + (size_t)r*Astr + c4*4);
                B4 h, l;
                split1(v.x, h.b[0], l.b[0]); split1(v.y, h.b[1], l.b[1]);
                split1(v.z, h.b[2], l.b[2]); split1(v.w, h.b[3], l.b[3]);
                int so = r*ASB + c4*8;
                *(uint2*)(sm + PV_PH + so) = h.u;
                *(uint2*)(sm + PV_PL + so) = l.u;
            }
        }
        // stage B: 64 rows (d) x 64 bf16 from VT / EvT
        {
            const __nv_bfloat16 *Bh, *Bl;
            size_t Bstr;
            if (s < 32) { Bh = g_VTh + (size_t)bh*HDn*Sn + s*64;
                          Bl = g_VTl + (size_t)bh*HDn*Sn + s*64;  Bstr = Sn; }
            else        { Bh = g_EvTh + (s-32)*64;
                          Bl = g_EvTl + (s-32)*64;                Bstr = WBS; }
            for (int it = tid; it < 512; it += 256) {
                int r = it >> 3, c = it & 7;
                int so = r*ASB + c*16;
                *(uint4*)(sm + PV_VH + so) = *(const uint4*)(Bh + (size_t)r*Bstr + c*8);
                *(uint4*)(sm + PV_VL + so) = *(const uint4*)(Bl + (size_t)r*Bstr + c*8);
            }
        }
        __syncthreads();

        const uint32_t abase[3] = { sb + PV_PH, sb + PV_PH, sb + PV_PL };
        const uint32_t bbase[3] = { sb + PV_VH, sb + PV_VL, sb + PV_VH };
        #pragma unroll
        for (int t = 0; t < 3; t++) {
            #pragma unroll
            for (int kt = 0; kt < 4; kt++) {
                uint32_t koff = kt*32;
                uint32_t a[2][4];
                #pragma unroll
                for (int mi = 0; mi < 2; mi++)
                    ldsm_x4(a[mi][0], a[mi][1], a[mi][2], a[mi][3],
                            abase[t] + (uint32_t)(m0 + mi*16)*ASB + koff + loff);
                uint32_t b[2][4];
                #pragma unroll
                for (int bi = 0; bi < 2; bi++)
                    ldsm_x4(b[bi][0], b[bi][1], b[bi][2], b[bi][3],
                            bbase[t] + (uint32_t)(n0 + bi*16)*ASB + koff + loff);
                #pragma unroll
                for (int mi = 0; mi < 2; mi++) {
                    mma16816(acc[mi][0], a[mi], b[0][0], b[0][2]);
                    mma16816(acc[mi][1], a[mi], b[0][1], b[0][3]);
                    mma16816(acc[mi][2], a[mi], b[1][0], b[1][2]);
                    mma16816(acc[mi][3], a[mi], b[1][1], b[1][3]);
                }
            }
        }
        __syncthreads();
    }

    // epilogue: write O fragments
    #pragma unroll
    for (int mi = 0; mi < 2; mi++) {
        int row = i0 + m0 + mi*16 + (lane >> 2);
        float* base0 = g_O + ((size_t)bh*Sn + row)*HDn;
        float* base1 = base0 + 8*(size_t)HDn;
        #pragma unroll
        for (int ni = 0; ni < 4; ni++) {
            int col = n0 + ni*8 + (lane & 3)*2;
            *(float2*)(base0 + col) = make_float2(acc[mi][ni][0], acc[mi][ni][1]);
            *(float2*)(base1 + col) = make_float2(acc[mi][ni][2], acc[mi][ni][3]);
        }
    }
}

// ============================================================================
// Kernel: out = concat(O) @ Wo + bo  (FFMA)
// ============================================================================
__global__ __launch_bounds__(256)
void outproj_kernel(const float* __restrict__ Wo,
                    const float* __restrict__ bo,
                    float* __restrict__ out)
{
    __shared__ float As[32][68];
    __shared__ float Bs[32][68];

    int m0 = blockIdx.y * 64;
    int n0 = blockIdx.x * 64;
    int tid = threadIdx.x;
    int tx = tid & 15, ty = tid >> 4;

    float acc[4][4] = {};
    for (int k0 = 0; k0 < DMn; k0 += 32) {
        for (int i = tid; i < 64*32; i += 256) {
            int m = i >> 5, k = i & 31;
            int row = m0 + m;
            int b = row / Sn, s = row % Sn;
            int c = k0 + k;
            int h = c >> 6, d = c & 63;
            As[k][m] = g_O[(((size_t)(b*Hn + h))*Sn + s)*HDn + d];
        }
        for (int i = tid; i < 32*64; i += 256) {
            int k = i >> 6, n = i & 63;
            Bs[k][n] = Wo[(size_t)(k0 + k)*DMn + n0 + n];
        }
        __syncthreads();
        #pragma unroll
        for (int kk = 0; kk < 32; kk++) {
            float av[4], bv[4];
            *(float4*)av = *(const float4*)&As[kk][ty*4];
            *(float4*)bv = *(const float4*)&Bs[kk][tx*4];
            #pragma unroll
            for (int i = 0; i < 4; i++)
                #pragma unroll
                for (int j = 0; j < 4; j++)
                    acc[i][j] += av[i]*bv[j];
        }
        __syncthreads();
    }
    #pragma unroll
    for (int i = 0; i < 4; i++) {
        int row = m0 + ty*4 + i;
        #pragma unroll
        for (int j = 0; j < 4; j++) {
            int col = n0 + tx*4 + j;
            out[(size_t)row*DMn + col] = acc[i][j] + bo[col];
        }
    }
}

// ============================================================================
extern "C" void kernel_launch(void* const* d_in, const int* in_sizes, int n_in,
                              void* d_out, int out_size)
{
    const float* query = (const float*)d_in[0];
    const float* value = (const float*)d_in[1];
    const float* Wq    = (const float*)d_in[2];
    const float* Wk    = (const float*)d_in[3];
    const float* Wv    = (const float*)d_in[4];
    const float* Wo    = (const float*)d_in[5];
    const float* bo    = (const float*)d_in[6];
    const float* Ek    = (const float*)d_in[7];
    const float* Ev    = (const float*)d_in[8];
    float* out = (float*)d_out;

    const int OUT_ELEMS = Bn*Sn*DMn;
    float* attn = out + (size_t)OUT_ELEMS;   // alpha scratch -> final attn weights

    cudaFuncSetAttribute(alpha_kernel,   cudaFuncAttributeMaxDynamicSharedMemorySize, AK_BYTES);
    cudaFuncSetAttribute(pv_kernel,      cudaFuncAttributeMaxDynamicSharedMemorySize, PV_BYTES);
    cudaFuncSetAttribute(softmax_kernel, cudaFuncAttributeMaxDynamicSharedMemorySize, (int)sizeof(SoftSmem));

    // 1) QKV projections (FFMA)
    dim3 pg(DMn/64, (Bn*Sn)/64, 3);
    proj_kernel<<<pg, 256>>>(query, value, Wq, Wk, Wv);

    // 2) conversions
    conv_qk_kernel<<<512, 256>>>();
    conv_vt_kernel<<<dim3(Sn/64, BHn), 256>>>();
    conv_ev_kernel<<<1, 256>>>(Ev);

    // 3) raw logits (tensor cores, mma.sync)
    alpha_kernel<<<dim3(Sn/128, Sn/128, BHn), 256, AK_BYTES>>>(attn);

    // 4) softmax + rel + bucket sums
    softmax_kernel<<<dim3(Sn/BI, BHn), 256, sizeof(SoftSmem)>>>(Ek, attn);

    // 5) O = P·V + Wb·Ev (tensor cores, mma.sync)
    pv_kernel<<<dim3(Sn/128, BHn), 256, PV_BYTES>>>(attn);

    // 6) output projection (FFMA)
    dim3 og(DMn/64, (Bn*Sn)/64);
    outproj_kernel<<<og, 256>>>(Wo, bo, out);
}

// round 6
// speedup vs baseline: 2.5416x; 1.4824x over previous
#include <cuda_runtime.h>
#include <cuda_bf16.h>
#include <cstdint>

#define Bn   2
#define Sn   2048
#define Hn   8
#define DMn  512
#define HDn  64
#define NRn  513
#define BHn  (Bn*Hn)
#define WBS  576     // padded stride for Wb / EvT
#define RSTR 640     // padded stride for REL rows
#define NIN  (Bn*Sn*DMn)   // 2M elements per input matrix

// ---------------- scratch ----------------
__device__ float g_REL[(size_t)BHn*Sn*RSTR];   // 84 MB fp32 rel logits
__device__ float g_Wb[(size_t)BHn*Sn*WBS];     // 75 MB bucket sums

__device__ __nv_bfloat16 g_INh[2*NIN], g_INl[2*NIN];          // query | value splits
__device__ __nv_bfloat16 g_WTh[4*DMn*DMn], g_WTl[4*DMn*DMn];  // Wq,Wk,Wv,Wo transposed [n][k]
__device__ __nv_bfloat16 g_Qh[BHn*Sn*HDn], g_Ql[BHn*Sn*HDn];  // pre-scaled 1/8
__device__ __nv_bfloat16 g_Kh[BHn*Sn*HDn], g_Kl[BHn*Sn*HDn];
__device__ __nv_bfloat16 g_VTh[BHn*HDn*Sn], g_VTl[BHn*HDn*Sn]; // [bh][d][s]
__device__ __nv_bfloat16 g_Oh[BHn*Sn*HDn],  g_Ol[BHn*Sn*HDn];
__device__ __nv_bfloat16 g_Ekh[RSTR*HDn],  g_Ekl[RSTR*HDn];    // [r][d], zero pad
__device__ __nv_bfloat16 g_EvTh[HDn*WBS],  g_EvTl[HDn*WBS];    // [d][r], zero pad

// ============================================================================
// helpers
// ============================================================================
__device__ __forceinline__ uint32_t smem_u32(const void* p) {
    uint32_t a;
    asm("{ .reg .u64 t; cvta.to.shared.u64 t, %1; cvt.u32.u64 %0, t; }"
        : "=r"(a) : "l"(p));
    return a;
}
__device__ __forceinline__ void ldsm_x4(uint32_t& r0, uint32_t& r1,
                                        uint32_t& r2, uint32_t& r3,
                                        uint32_t addr) {
    asm volatile("ldmatrix.sync.aligned.m8n8.x4.shared.b16 {%0,%1,%2,%3}, [%4];"
                 : "=r"(r0), "=r"(r1), "=r"(r2), "=r"(r3) : "r"(addr));
}
__device__ __forceinline__ void mma16816(float* d, const uint32_t* a,
                                         uint32_t b0, uint32_t b1) {
    asm volatile(
        "mma.sync.aligned.m16n8k16.row.col.f32.bf16.bf16.f32 "
        "{%0,%1,%2,%3}, {%4,%5,%6,%7}, {%8,%9}, {%0,%1,%2,%3};"
        : "+f"(d[0]), "+f"(d[1]), "+f"(d[2]), "+f"(d[3])
        : "r"(a[0]), "r"(a[1]), "r"(a[2]), "r"(a[3]), "r"(b0), "r"(b1));
}

union B4 { __nv_bfloat16 b[4]; uint2 u; };

__device__ __forceinline__ void split1(float x, __nv_bfloat16& h, __nv_bfloat16& l) {
    h = __float2bfloat16(x);
    l = __float2bfloat16(x - __bfloat162float(h));
}
__device__ __forceinline__ void split2(float a, float b, uint32_t& hh, uint32_t& ll) {
    __nv_bfloat16 h0, l0, h1, l1;
    split1(a, h0, l0); split1(b, h1, l1);
    __nv_bfloat162 H; H.x = h0; H.y = h1;
    __nv_bfloat162 L; L.x = l0; L.y = l1;
    hh = *(uint32_t*)&H; ll = *(uint32_t*)&L;
}

#define ASB 144   // padded smem row stride bytes (64 bf16 + 16B pad)

// ============================================================================
// conv_in: split query & value fp32 -> hi/lo bf16
// ============================================================================
__global__ __launch_bounds__(256)
void conv_in_kernel(const float* __restrict__ query,
                    const float* __restrict__ value)
{
    const size_t N4 = NIN/4;
    size_t stride = (size_t)gridDim.x*blockDim.x;
    for (size_t i = (size_t)blockIdx.x*blockDim.x + threadIdx.x; i < N4; i += stride) {
        float4 q = ((const float4*)query)[i];
        B4 h, l;
        split1(q.x, h.b[0], l.b[0]); split1(q.y, h.b[1], l.b[1]);
        split1(q.z, h.b[2], l.b[2]); split1(q.w, h.b[3], l.b[3]);
        *(uint2*)&g_INh[4*i] = h.u; *(uint2*)&g_INl[4*i] = l.u;

        float4 v = ((const float4*)value)[i];
        split1(v.x, h.b[0], l.b[0]); split1(v.y, h.b[1], l.b[1]);
        split1(v.z, h.b[2], l.b[2]); split1(v.w, h.b[3], l.b[3]);
        *(uint2*)&g_INh[NIN + 4*i] = h.u; *(uint2*)&g_INl[NIN + 4*i] = l.u;
    }
}

// ============================================================================
// conv_w: transpose + split weights -> [n][k] bf16 hi/lo
// ============================================================================
__global__ __launch_bounds__(256)
void conv_w_kernel(const float* __restrict__ Wq, const float* __restrict__ Wk,
                   const float* __restrict__ Wv, const float* __restrict__ Wo)
{
    __shared__ float t[64][65];
    int w = blockIdx.z;
    const float* W = (w == 0) ? Wq : (w == 1) ? Wk : (w == 2) ? Wv : Wo;
    int k0 = blockIdx.y * 64;
    int n0 = blockIdx.x * 64;
    int tid = threadIdx.x;
    for (int idx = tid; idx < 64*64; idx += 256) {
        int r = idx >> 6, c = idx & 63;
        t[r][c] = W[(size_t)(k0 + r)*DMn + n0 + c];
    }
    __syncthreads();
    for (int idx = tid; idx < 64*32; idx += 256) {
        int nl = idx >> 5, kp = (idx & 31)*2;
        uint32_t hh, ll;
        split2(t[kp][nl], t[kp+1][nl], hh, ll);
        size_t o = (size_t)w*DMn*DMn + (size_t)(n0 + nl)*DMn + k0 + kp;
        *(uint32_t*)&g_WTh[o] = hh;
        *(uint32_t*)&g_WTl[o] = ll;
    }
}

// ============================================================================
// conv_misc: Ek -> [r][d] padded, Ev -> EvT [d][r] padded
// ============================================================================
__global__ __launch_bounds__(256)
void conv_misc_kernel(const float* __restrict__ Ek, const float* __restrict__ Ev)
{
    int stride = gridDim.x*blockDim.x;
    int tid = blockIdx.x*blockDim.x + threadIdx.x;
    for (int idx = tid; idx < RSTR*HDn; idx += stride) {
        int r = idx >> 6, d = idx & 63;
        float v = (r < NRn) ? Ek[(size_t)r*HDn + d] : 0.f;
        __nv_bfloat16 h, l; split1(v, h, l);
        g_Ekh[idx] = h; g_Ekl[idx] = l;
    }
    for (int idx = tid; idx < HDn*WBS; idx += stride) {
        int d = idx / WBS, r = idx - d*WBS;
        float v = (r < NRn) ? Ev[(size_t)r*HDn + d] : 0.f;
        __nv_bfloat16 h, l; split1(v, h, l);
        g_EvTh[idx] = h; g_EvTl[idx] = l;
    }
}

// ============================================================================
// proj_mma: C = A @ W (bf16 3-term), t=0 Q (x1/8), t=1 K, t=2 V (transposed out)
// ============================================================================
#define PJ_AH 0
#define PJ_AL (128*ASB)
#define PJ_BH (2*128*ASB)
#define PJ_BL (3*128*ASB)
#define PJ_BYTES (4*128*ASB)   // 73728

__global__ __launch_bounds__(256)
void proj_mma_kernel()
{
    extern __shared__ char sm[];
    uint32_t sb = smem_u32(sm);
    const int tid  = threadIdx.x;
    const int lane = tid & 31;
    const int warp = tid >> 5;
    const int t  = blockIdx.z;
    const int m0g = blockIdx.y * 128;
    const int n0g = blockIdx.x * 128;

    const __nv_bfloat16* Ah = g_INh + (t ? NIN : 0);
    const __nv_bfloat16* Al = g_INl + (t ? NIN : 0);
    const __nv_bfloat16* Bh = g_WTh + (size_t)t*DMn*DMn;
    const __nv_bfloat16* Bl = g_WTl + (size_t)t*DMn*DMn;

    const int m0 = (warp >> 2) * 64;
    const int n0 = (warp & 3) * 32;
    const uint32_t loff = (uint32_t)((lane & 15)*ASB + (lane >> 4)*16);

    float acc[4][4][4] = {};

    for (int kc = 0; kc < 8; kc++) {
        for (int it = tid; it < 1024; it += 256) {
            int r = it >> 3, c = it & 7;
            int so = r*ASB + c*16;
            size_t ga = (size_t)(m0g + r)*DMn + kc*64 + c*8;
            size_t gb = (size_t)(n0g + r)*DMn + kc*64 + c*8;
            *(uint4*)(sm + PJ_AH + so) = *(const uint4*)(Ah + ga);
            *(uint4*)(sm + PJ_AL + so) = *(const uint4*)(Al + ga);
            *(uint4*)(sm + PJ_BH + so) = *(const uint4*)(Bh + gb);
            *(uint4*)(sm + PJ_BL + so) = *(const uint4*)(Bl + gb);
        }
        __syncthreads();

        const uint32_t abase[3] = { sb + PJ_AH, sb + PJ_AH, sb + PJ_AL };
        const uint32_t bbase[3] = { sb + PJ_BH, sb + PJ_BL, sb + PJ_BH };
        #pragma unroll
        for (int tt = 0; tt < 3; tt++) {
            #pragma unroll
            for (int kt = 0; kt < 4; kt++) {
                uint32_t koff = kt*32;
                uint32_t a[4][4];
                #pragma unroll
                for (int mi = 0; mi < 4; mi++)
                    ldsm_x4(a[mi][0], a[mi][1], a[mi][2], a[mi][3],
                            abase[tt] + (uint32_t)(m0 + mi*16)*ASB + koff + loff);
                uint32_t b[2][4];
                #pragma unroll
                for (int bi = 0; bi < 2; bi++)
                    ldsm_x4(b[bi][0], b[bi][1], b[bi][2], b[bi][3],
                            bbase[tt] + (uint32_t)(n0 + bi*16)*ASB + koff + loff);
                #pragma unroll
                for (int mi = 0; mi < 4; mi++) {
                    mma16816(acc[mi][0], a[mi], b[0][0], b[0][2]);
                    mma16816(acc[mi][1], a[mi], b[0][1], b[0][3]);
                    mma16816(acc[mi][2], a[mi], b[1][0], b[1][2]);
                    mma16816(acc[mi][3], a[mi], b[1][1], b[1][3]);
                }
            }
        }
        __syncthreads();
    }

    if (t < 2) {
        const float scale = (t == 0) ? 0.125f : 1.0f;
        __nv_bfloat16* Dh = (t == 0) ? g_Qh : g_Kh;
        __nv_bfloat16* Dl = (t == 0) ? g_Ql : g_Kl;
        #pragma unroll
        for (int mi = 0; mi < 4; mi++) {
            #pragma unroll
            for (int rr = 0; rr < 2; rr++) {
                int row = m0g + m0 + mi*16 + rr*8 + (lane >> 2);
                int b = row >> 11, s = row & 2047;
                #pragma unroll
                for (int ni = 0; ni < 4; ni++) {
                    int colg = n0g + n0 + ni*8 + (lane & 3)*2;
                    int h = colg >> 6, d = colg & 63;
                    size_t addr = (((size_t)(b*Hn + h))*Sn + s)*HDn + d;
                    uint32_t hh, ll;
                    split2(acc[mi][ni][rr*2 + 0]*scale, acc[mi][ni][rr*2 + 1]*scale, hh, ll);
                    *(uint32_t*)&Dh[addr] = hh;
                    *(uint32_t*)&Dl[addr] = ll;
                }
            }
        }
    } else {
        // V: stage fp32 tile, transpose-write VT hi/lo
        float* stage = (float*)sm;   // 128 x 132 floats = 67584 B <= PJ_BYTES
        #pragma unroll
        for (int mi = 0; mi < 4; mi++) {
            #pragma unroll
            for (int rr = 0; rr < 2; rr++) {
                int rl = m0 + mi*16 + rr*8 + (lane >> 2);
                #pragma unroll
                for (int ni = 0; ni < 4; ni++) {
                    int cl = n0 + ni*8 + (lane & 3)*2;
                    *(float2*)&stage[rl*132 + cl] =
                        make_float2(acc[mi][ni][rr*2 + 0], acc[mi][ni][rr*2 + 1]);
                }
            }
        }
        __syncthreads();
        int b  = m0g >> 11;
        int s0 = m0g & 2047;
        for (int idx = tid; idx < 128*64; idx += 256) {
            int c = idx >> 6, sp = idx & 63;
            int sl = sp*2;
            int colg = n0g + c;
            int h = colg >> 6, d = colg & 63;
            uint32_t hh, ll;
            split2(stage[sl*132 + c], stage[(sl+1)*132 + c], hh, ll);
            size_t addr = ((size_t)((b*Hn + h)*HDn + d))*Sn + s0 + sl;
            *(uint32_t*)&g_VTh[addr] = hh;
            *(uint32_t*)&g_VTl[addr] = ll;
        }
    }
}

// ============================================================================
// rel_mma: REL[bh][i][r] = Q[i]·Ek[r]  (fp32 out, stride RSTR)
// ============================================================================
__global__ __launch_bounds__(256)
void rel_mma_kernel()
{
    extern __shared__ char sm[];
    uint32_t sb = smem_u32(sm);
    const int tid  = threadIdx.x;
    const int lane = tid & 31;
    const int warp = tid >> 5;
    const int bh = blockIdx.z;
    const int i0 = blockIdx.y * 128;
    const int j0 = blockIdx.x * 128;   // r offset, < 640

    {
        const uint4* qh = (const uint4*)(g_Qh + ((size_t)bh*Sn + i0)*HDn);
        const uint4* ql = (const uint4*)(g_Ql + ((size_t)bh*Sn + i0)*HDn);
        const uint4* eh = (const uint4*)(g_Ekh + (size_t)j0*HDn);
        const uint4* el = (const uint4*)(g_Ekl + (size_t)j0*HDn);
        for (int it = tid; it < 1024; it += 256) {
            int r = it >> 3, c = it & 7;
            int so = r*ASB + c*16;
            *(uint4*)(sm + PJ_AH + so) = qh[it];
            *(uint4*)(sm + PJ_AL + so) = ql[it];
            *(uint4*)(sm + PJ_BH + so) = eh[it];
            *(uint4*)(sm + PJ_BL + so) = el[it];
        }
    }
    __syncthreads();

    const int m0 = (warp >> 2) * 64;
    const int n0 = (warp & 3) * 32;
    const uint32_t loff = (uint32_t)((lane & 15)*ASB + (lane >> 4)*16);

    float acc[4][4][4] = {};
    const uint32_t abase[3] = { sb + PJ_AH, sb + PJ_AH, sb + PJ_AL };
    const uint32_t bbase[3] = { sb + PJ_BH, sb + PJ_BL, sb + PJ_BH };
    #pragma unroll
    for (int tt = 0; tt < 3; tt++) {
        #pragma unroll
        for (int kt = 0; kt < 4; kt++) {
            uint32_t koff = kt*32;
            uint32_t a[4][4];
            #pragma unroll
            for (int mi = 0; mi < 4; mi++)
                ldsm_x4(a[mi][0], a[mi][1], a[mi][2], a[mi][3],
                        abase[tt] + (uint32_t)(m0 + mi*16)*ASB + koff + loff);
            uint32_t b[2][4];
            #pragma unroll
            for (int bi = 0; bi < 2; bi++)
                ldsm_x4(b[bi][0], b[bi][1], b[bi][2], b[bi][3],
                        bbase[tt] + (uint32_t)(n0 + bi*16)*ASB + koff + loff);
            #pragma unroll
            for (int mi = 0; mi < 4; mi++) {
                mma16816(acc[mi][0], a[mi], b[0][0], b[0][2]);
                mma16816(acc[mi][1], a[mi], b[0][1], b[0][3]);
                mma16816(acc[mi][2], a[mi], b[1][0], b[1][2]);
                mma16816(acc[mi][3], a[mi], b[1][1], b[1][3]);
            }
        }
    }

    #pragma unroll
    for (int mi = 0; mi < 4; mi++) {
        int row = i0 + m0 + mi*16 + (lane >> 2);
        float* base0 = g_REL + ((size_t)bh*Sn + row)*RSTR + j0;
        float* base1 = base0 + 8*(size_t)RSTR;
        #pragma unroll
        for (int ni = 0; ni < 4; ni++) {
            int col = n0 + ni*8 + (lane & 3)*2;
            *(float2*)(base0 + col) = make_float2(acc[mi][ni][0], acc[mi][ni][1]);
            *(float2*)(base1 + col) = make_float2(acc[mi][ni][2], acc[mi][ni][3]);
        }
    }
}

// ============================================================================
// alpha kernel: alpha[128 x 128] = Q·K^T (bf16 3-term)
// ============================================================================
__global__ __launch_bounds__(256)
void alpha_kernel(float* __restrict__ alpha_out)
{
    extern __shared__ char sm[];
    uint32_t sb = smem_u32(sm);
    const int tid  = threadIdx.x;
    const int lane = tid & 31;
    const int warp = tid >> 5;
    const int bh = blockIdx.z;
    const int i0 = blockIdx.y * 128;
    const int j0 = blockIdx.x * 128;

    {
        const uint4* qh = (const uint4*)(g_Qh + ((size_t)bh*Sn + i0)*HDn);
        const uint4* ql = (const uint4*)(g_Ql + ((size_t)bh*Sn + i0)*HDn);
        const uint4* kh = (const uint4*)(g_Kh + ((size_t)bh*Sn + j0)*HDn);
        const uint4* kl = (const uint4*)(g_Kl + ((size_t)bh*Sn + j0)*HDn);
        for (int it = tid; it < 1024; it += 256) {
            int r = it >> 3, c = it & 7;
            int so = r*ASB + c*16;
            *(uint4*)(sm + PJ_AH + so) = qh[it];
            *(uint4*)(sm + PJ_AL + so) = ql[it];
            *(uint4*)(sm + PJ_BH + so) = kh[it];
            *(uint4*)(sm + PJ_BL + so) = kl[it];
        }
    }
    __syncthreads();

    const int m0 = (warp >> 2) * 64;
    const int n0 = (warp & 3) * 32;
    const uint32_t loff = (uint32_t)((lane & 15)*ASB + (lane >> 4)*16);

    float acc[4][4][4] = {};
    const uint32_t abase[3] = { sb + PJ_AH, sb + PJ_AH, sb + PJ_AL };
    const uint32_t bbase[3] = { sb + PJ_BH, sb + PJ_BL, sb + PJ_BH };
    #pragma unroll
    for (int tt = 0; tt < 3; tt++) {
        #pragma unroll
        for (int kt = 0; kt < 4; kt++) {
            uint32_t koff = kt*32;
            uint32_t a[4][4];
            #pragma unroll
            for (int mi = 0; mi < 4; mi++)
                ldsm_x4(a[mi][0], a[mi][1], a[mi][2], a[mi][3],
                        abase[tt] + (uint32_t)(m0 + mi*16)*ASB + koff + loff);
            uint32_t b[2][4];
            #pragma unroll
            for (int bi = 0; bi < 2; bi++)
                ldsm_x4(b[bi][0], b[bi][1], b[bi][2], b[bi][3],
                        bbase[tt] + (uint32_t)(n0 + bi*16)*ASB + koff + loff);
            #pragma unroll
            for (int mi = 0; mi < 4; mi++) {
                mma16816(acc[mi][0], a[mi], b[0][0], b[0][2]);
                mma16816(acc[mi][1], a[mi], b[0][1], b[0][3]);
                mma16816(acc[mi][2], a[mi], b[1][0], b[1][2]);
                mma16816(acc[mi][3], a[mi], b[1][1], b[1][3]);
            }
        }
    }

    #pragma unroll
    for (int mi = 0; mi < 4; mi++) {
        int row = i0 + m0 + mi*16 + (lane >> 2);
        float* base0 = alpha_out + ((size_t)bh*Sn + row)*Sn + j0;
        float* base1 = base0 + 8*(size_t)Sn;
        #pragma unroll
        for (int ni = 0; ni < 4; ni++) {
            int col = n0 + ni*8 + (lane & 3)*2;
            *(float2*)(base0 + col) = make_float2(acc[mi][ni][0], acc[mi][ni][1]);
            *(float2*)(base1 + col) = make_float2(acc[mi][ni][2], acc[mi][ni][3]);
        }
    }
}

// ============================================================================
// softmax kernel (BI=8): load alpha + REL gather, exact softmax, write p + Wb
// ============================================================================
#define BI 8
struct SoftSmem {
    float A[BI][Sn];      // 65536
    float W[BI][520];     // 16640
    float rsum[BI];
};

__global__ __launch_bounds__(256)
void softmax_kernel(float* __restrict__ attn)
{
    extern __shared__ char smem_raw[];
    SoftSmem& sm = *reinterpret_cast<SoftSmem*>(smem_raw);

    const int bh = blockIdx.y;
    const int i0 = blockIdx.x * BI;
    const int tid  = threadIdx.x;
    const int lane = tid & 31;
    const int warp = tid >> 5;

    // load REL rows
    for (int idx = tid; idx < BI*520; idx += 256) {
        int ii = idx / 520, r = idx - ii*520;
        sm.W[ii][r] = (r < NRn) ? g_REL[((size_t)bh*Sn + i0 + ii)*RSTR + r] : 0.f;
    }
    __syncthreads();

    // alpha + rel gather
    {
        const float* araw = attn + ((size_t)bh*Sn + i0)*Sn;
        for (int idx = tid; idx < BI*(Sn/4); idx += 256) {
            int ii = idx >> 9;
            int j4 = (idx & 511)*4;
            float4 v = *(const float4*)(araw + (size_t)ii*Sn + j4);
            int i = i0 + ii;
            v.x += sm.W[ii][min(256, max(-256, j4     - i)) + 256];
            v.y += sm.W[ii][min(256, max(-256, j4 + 1 - i)) + 256];
            v.z += sm.W[ii][min(256, max(-256, j4 + 2 - i)) + 256];
            v.w += sm.W[ii][min(256, max(-256, j4 + 3 - i)) + 256];
            *(float4*)&sm.A[ii][j4] = v;
        }
    }
    __syncthreads();

    // softmax: each warp owns 1 row
    {
        int ii = warp;
        float m = -1e30f;
        for (int j = lane; j < Sn; j += 32) m = fmaxf(m, sm.A[ii][j]);
        #pragma unroll
        for (int o = 16; o; o >>= 1) m = fmaxf(m, __shfl_xor_sync(0xFFFFFFFFu, m, o));
        float ssum = 0.f;
        for (int j = lane; j < Sn; j += 32) {
            float p = __expf(sm.A[ii][j] - m);
            sm.A[ii][j] = p;
            ssum += p;
        }
        #pragma unroll
        for (int o = 16; o; o >>= 1) ssum += __shfl_xor_sync(0xFFFFFFFFu, ssum, o);
        if (lane == 0) sm.rsum[ii] = ssum;
    }
    __syncthreads();

    // normalize + write p
    {
        float4* A4 = reinterpret_cast<float4*>(&sm.A[0][0]);
        for (int idx = tid; idx < BI*(Sn/4); idx += 256) {
            int ii = idx >> 9;
            float inv = 1.0f / sm.rsum[ii];
            float4 v = A4[idx];
            v.x *= inv; v.y *= inv; v.z *= inv; v.w *= inv;
            A4[idx] = v;
            reinterpret_cast<float4*>(attn + ((size_t)bh*Sn + i0 + ii)*Sn)[idx & 511] = v;
        }
    }
    __syncthreads();

    // bucket sums
    for (int idx = tid; idx < BI*511; idx += 256) {
        int ii = idx / 511;
        int r  = idx % 511 + 1;
        int j  = i0 + ii + r - 256;
        sm.W[ii][r] = (j >= 0 && j < Sn) ? sm.A[ii][j] : 0.f;
    }
    {
        int ii = warp;
        int i  = i0 + ii;
        float s0 = 0.f, s1 = 0.f;
        for (int j = lane; j <= i - 256; j += 32) s0 += sm.A[ii][j];
        for (int j = i + 256 + lane; j < Sn; j += 32) s1 += sm.A[ii][j];
        #pragma unroll
        for (int o = 16; o; o >>= 1) {
            s0 += __shfl_xor_sync(0xFFFFFFFFu, s0, o);
            s1 += __shfl_xor_sync(0xFFFFFFFFu, s1, o);
        }
        if (lane == 0) { sm.W[ii][0] = s0; sm.W[ii][512] = s1; }
    }
    __syncthreads();

    for (int idx = tid; idx < BI*WBS; idx += 256) {
        int ii = idx / WBS, r = idx - ii*WBS;
        g_Wb[((size_t)bh*Sn + i0 + ii)*WBS + r] = (r < NRn) ? sm.W[ii][r] : 0.f;
    }
}

// ============================================================================
// pv kernel: O[128 x 64] = P·V + Wb·Ev (bf16 3-term), epilogue -> Oh/Ol
// ============================================================================
#define PV_PH 0
#define PV_PL (128*ASB)
#define PV_VH (2*128*ASB)
#define PV_VL (2*128*ASB + 64*ASB)
#define PV_BYTES (2*128*ASB + 2*64*ASB)   // 55296

__global__ __launch_bounds__(256)
void pv_kernel(const float* __restrict__ attn)
{
    extern __shared__ char sm[];
    uint32_t sb = smem_u32(sm);
    const int tid  = threadIdx.x;
    const int lane = tid & 31;
    const int warp = tid >> 5;
    const int bh = blockIdx.y;
    const int i0 = blockIdx.x * 128;

    const int m0 = (warp >> 1) * 32;
    const int n0 = (warp & 1) * 32;
    const uint32_t loff = (uint32_t)((lane & 15)*ASB + (lane >> 4)*16);

    float acc[2][4][4] = {};

    const int NCHUNK = 32 + WBS/64;    // 41
    for (int s = 0; s < NCHUNK; s++) {
        {
            const float* Abase;
            size_t Astr;
            if (s < 32) { Abase = attn + ((size_t)bh*Sn + i0)*Sn + s*64;        Astr = Sn; }
            else        { Abase = g_Wb + ((size_t)bh*Sn + i0)*WBS + (s-32)*64;  Astr = WBS; }
            for (int it = tid; it < 2048; it += 256) {
                int r = it >> 4, c4 = it & 15;
                float4 v = *(const float4*)(Abase + (size_t)r*Astr + c4*4);
                B4 h, l;
                split1(v.x, h.b[0], l.b[0]); split1(v.y, h.b[1], l.b[1]);
                split1(v.z, h.b[2], l.b[2]); split1(v.w, h.b[3], l.b[3]);
                int so = r*ASB + c4*8;
                *(uint2*)(sm + PV_PH + so) = h.u;
                *(uint2*)(sm + PV_PL + so) = l.u;
            }
        }
        {
            const __nv_bfloat16 *Bh, *Bl;
            size_t Bstr;
            if (s < 32) { Bh = g_VTh + (size_t)bh*HDn*Sn + s*64;
                          Bl = g_VTl + (size_t)bh*HDn*Sn + s*64;  Bstr = Sn; }
            else        { Bh = g_EvTh + (s-32)*64;
                          Bl = g_EvTl + (s-32)*64;                Bstr = WBS; }
            for (int it = tid; it < 512; it += 256) {
                int r = it >> 3, c = it & 7;
                int so = r*ASB + c*16;
                *(uint4*)(sm + PV_VH + so) = *(const uint4*)(Bh + (size_t)r*Bstr + c*8);
                *(uint4*)(sm + PV_VL + so) = *(const uint4*)(Bl + (size_t)r*Bstr + c*8);
            }
        }
        __syncthreads();

        const uint32_t abase[3] = { sb + PV_PH, sb + PV_PH, sb + PV_PL };
        const uint32_t bbase[3] = { sb + PV_VH, sb + PV_VL, sb + PV_VH };
        #pragma unroll
        for (int t = 0; t < 3; t++) {
            #pragma unroll
            for (int kt = 0; kt < 4; kt++) {
                uint32_t koff = kt*32;
                uint32_t a[2][4];
                #pragma unroll
                for (int mi = 0; mi < 2; mi++)
                    ldsm_x4(a[mi][0], a[mi][1], a[mi][2], a[mi][3],
                            abase[t] + (uint32_t)(m0 + mi*16)*ASB + koff + loff);
                uint32_t b[2][4];
                #pragma unroll
                for (int bi = 0; bi < 2; bi++)
                    ldsm_x4(b[bi][0], b[bi][1], b[bi][2], b[bi][3],
                            bbase[t] + (uint32_t)(n0 + bi*16)*ASB + koff + loff);
                #pragma unroll
                for (int mi = 0; mi < 2; mi++) {
                    mma16816(acc[mi][0], a[mi], b[0][0], b[0][2]);
                    mma16816(acc[mi][1], a[mi], b[0][1], b[0][3]);
                    mma16816(acc[mi][2], a[mi], b[1][0], b[1][2]);
                    mma16816(acc[mi][3], a[mi], b[1][1], b[1][3]);
                }
            }
        }
        __syncthreads();
    }

    // epilogue: split O fragments -> Oh/Ol
    #pragma unroll
    for (int mi = 0; mi < 2; mi++) {
        #pragma unroll
        for (int rr = 0; rr < 2; rr++) {
            int row = i0 + m0 + mi*16 + rr*8 + (lane >> 2);
            size_t base = ((size_t)bh*Sn + row)*HDn;
            #pragma unroll
            for (int ni = 0; ni < 4; ni++) {
                int col = n0 + ni*8 + (lane & 3)*2;
                uint32_t hh, ll;
                split2(acc[mi][ni][rr*2 + 0], acc[mi][ni][rr*2 + 1], hh, ll);
                *(uint32_t*)&g_Oh[base + col] = hh;
                *(uint32_t*)&g_Ol[base + col] = ll;
            }
        }
    }
}

// ============================================================================
// outproj_mma: out = O @ Wo + bo (bf16 3-term)
// ============================================================================
__global__ __launch_bounds__(256)
void outproj_mma_kernel(const float* __restrict__ bo, float* __restrict__ out)
{
    extern __shared__ char sm[];
    uint32_t sb = smem_u32(sm);
    const int tid  = threadIdx.x;
    const int lane = tid & 31;
    const int warp = tid >> 5;
    const int m0g = blockIdx.y * 128;
    const int n0g = blockIdx.x * 128;

    const __nv_bfloat16* Bh = g_WTh + (size_t)3*DMn*DMn;
    const __nv_bfloat16* Bl = g_WTl + (size_t)3*DMn*DMn;

    const int m0 = (warp >> 2) * 64;
    const int n0 = (warp & 3) * 32;
    const uint32_t loff = (uint32_t)((lane & 15)*ASB + (lane >> 4)*16);

    float acc[4][4][4] = {};
    const int b = m0g >> 11;

    for (int kc = 0; kc < 8; kc++) {   // kc = head index
        for (int it = tid; it < 1024; it += 256) {
            int r = it >> 3, c = it & 7;
            int so = r*ASB + c*16;
            int s = (m0g & 2047) + r;
            size_t ga = (((size_t)(b*Hn + kc))*Sn + s)*HDn + c*8;
            size_t gb = (size_t)(n0g + r)*DMn + kc*64 + c*8;
            *(uint4*)(sm + PJ_AH + so) = *(const uint4*)(g_Oh + ga);
            *(uint4*)(sm + PJ_AL + so) = *(const uint4*)(g_Ol + ga);
            *(uint4*)(sm + PJ_BH + so) = *(const uint4*)(Bh + gb);
            *(uint4*)(sm + PJ_BL + so) = *(const uint4*)(Bl + gb);
        }
        __syncthreads();

        const uint32_t abase[3] = { sb + PJ_AH, sb + PJ_AH, sb + PJ_AL };
        const uint32_t bbase[3] = { sb + PJ_BH, sb + PJ_BL, sb + PJ_BH };
        #pragma unroll
        for (int tt = 0; tt < 3; tt++) {
            #pragma unroll
            for (int kt = 0; kt < 4; kt++) {
                uint32_t koff = kt*32;
                uint32_t a[4][4];
                #pragma unroll
                for (int mi = 0; mi < 4; mi++)
                    ldsm_x4(a[mi][0], a[mi][1], a[mi][2], a[mi][3],
                            abase[tt] + (uint32_t)(m0 + mi*16)*ASB + koff + loff);
                uint32_t bfr[2][4];
                #pragma unroll
                for (int bi = 0; bi < 2; bi++)
                    ldsm_x4(bfr[bi][0], bfr[bi][1], bfr[bi][2], bfr[bi][3],
                            bbase[tt] + (uint32_t)(n0 + bi*16)*ASB + koff + loff);
                #pragma unroll
                for (int mi = 0; mi < 4; mi++) {
                    mma16816(acc[mi][0], a[mi], bfr[0][0], bfr[0][2]);
                    mma16816(acc[mi][1], a[mi], bfr[0][1], bfr[0][3]);
                    mma16816(acc[mi][2], a[mi], bfr[1][0], bfr[1][2]);
                    mma16816(acc[mi][3], a[mi], bfr[1][1], bfr[1][3]);
                }
            }
        }
        __syncthreads();
    }

    #pragma unroll
    for (int mi = 0; mi < 4; mi++) {
        int row = m0g + m0 + mi*16 + (lane >> 2);
        float* base0 = out + (size_t)row*DMn + n0g;
        float* base1 = base0 + 8*(size_t)DMn;
        #pragma unroll
        for (int ni = 0; ni < 4; ni++) {
            int col = n0 + ni*8 + (lane & 3)*2;
            float b0 = bo[n0g + col], b1 = bo[n0g + col + 1];
            *(float2*)(base0 + col) = make_float2(acc[mi][ni][0] + b0, acc[mi][ni][1] + b1);
            *(float2*)(base1 + col) = make_float2(acc[mi][ni][2] + b0, acc[mi][ni][3] + b1);
        }
    }
}

// ============================================================================
extern "C" void kernel_launch(void* const* d_in, const int* in_sizes, int n_in,
                              void* d_out, int out_size)
{
    const float* query = (const float*)d_in[0];
    const float* value = (const float*)d_in[1];
    const float* Wq    = (const float*)d_in[2];
    const float* Wk    = (const float*)d_in[3];
    const float* Wv    = (const float*)d_in[4];
    const float* Wo    = (const float*)d_in[5];
    const float* bo    = (const float*)d_in[6];
    const float* Ek    = (const float*)d_in[7];
    const float* Ev    = (const float*)d_in[8];
    float* out = (float*)d_out;

    const int OUT_ELEMS = Bn*Sn*DMn;
    float* attn = out + (size_t)OUT_ELEMS;

    cudaFuncSetAttribute(proj_mma_kernel,    cudaFuncAttributeMaxDynamicSharedMemorySize, PJ_BYTES);
    cudaFuncSetAttribute(rel_mma_kernel,     cudaFuncAttributeMaxDynamicSharedMemorySize, PJ_BYTES);
    cudaFuncSetAttribute(alpha_kernel,       cudaFuncAttributeMaxDynamicSharedMemorySize, PJ_BYTES);
    cudaFuncSetAttribute(outproj_mma_kernel, cudaFuncAttributeMaxDynamicSharedMemorySize, PJ_BYTES);
    cudaFuncSetAttribute(pv_kernel,          cudaFuncAttributeMaxDynamicSharedMemorySize, PV_BYTES);
    cudaFuncSetAttribute(softmax_kernel,     cudaFuncAttributeMaxDynamicSharedMemorySize, (int)sizeof(SoftSmem));

    // conversions
    conv_in_kernel<<<512, 256>>>(query, value);
    conv_w_kernel<<<dim3(8, 8, 4), 256>>>(Wq, Wk, Wv, Wo);
    conv_misc_kernel<<<64, 256>>>(Ek, Ev);

    // projections (tensor)
    proj_mma_kernel<<<dim3(DMn/128, (Bn*Sn)/128, 3), 256, PJ_BYTES>>>();

    // rel logits (tensor)
    rel_mma_kernel<<<dim3(RSTR/128, Sn/128, BHn), 256, PJ_BYTES>>>();

    // raw QK logits (tensor)
    alpha_kernel<<<dim3(Sn/128, Sn/128, BHn), 256, PJ_BYTES>>>(attn);

    // softmax + bucket sums
    softmax_kernel<<<dim3(Sn/BI, BHn), 256, sizeof(SoftSmem)>>>(attn);

    // O = P·V + Wb·Ev (tensor)
    pv_kernel<<<dim3(Sn/128, BHn), 256, PV_BYTES>>>(attn);

    // output projection (tensor)
    outproj_mma_kernel<<<dim3(DMn/128, (Bn*Sn)/128), 256, PJ_BYTES>>>(bo, out);
}